// round 15
// baseline (speedup 1.0000x reference)
#include <cuda_runtime.h>
#include <cuda_fp16.h>
#include <cstdint>
#include <math.h>

#define NN   50000      // nodes
#define NE   800000     // edges
#define NFD  128        // node feature size
#define EFD  64         // edge feature size
#define LL   256        // layer size (mlp1 out)
#define DD1  193        // mlp1 input dim
#define DD2  385        // mlp2 dim
#define KXW  129        // x + batch part of mlp1 K
#define BNEPS 1e-5f

// ---------------- scratch (static device globals) ---------------------------
__device__ __half   g_Y1[(size_t)NE * LL];     // edge MLP pre-BN output (fp16)
__device__ __half   g_Y2[(size_t)NN * DD2];    // node MLP pre-BN output (fp16)
__device__ __half   g_XW[(size_t)NN * LL];     // node part of edge MLP (fp16)
__device__ float    g_ssum[(size_t)NN * LL];   // aggregated means
__device__ __half   g_W1e[LL * EFD];           // W1[129:193]^T as fp16, [n][k]
__device__ int      g_cnt[NN];
__device__ int      g_off[NN + 1];
__device__ int      g_cur[NN];
__device__ int      g_eid[NE];
__device__ float    g_sum1[LL],  g_sumsq1[LL],  g_scale1[LL],  g_shift1[LL];
__device__ float    g_sum2[DD2], g_sumsq2[DD2], g_scale2[DD2], g_shift2[DD2];

// ---------------- fp16 mma / ldmatrix helpers --------------------------------
__device__ __forceinline__ void mma_h(float* c, uint32_t a0, uint32_t a1,
                                      uint32_t a2, uint32_t a3,
                                      uint32_t b0, uint32_t b1) {
    asm volatile(
        "mma.sync.aligned.m16n8k16.row.col.f32.f16.f16.f32 "
        "{%0,%1,%2,%3},{%4,%5,%6,%7},{%8,%9},{%0,%1,%2,%3};"
        : "+f"(c[0]), "+f"(c[1]), "+f"(c[2]), "+f"(c[3])
        : "r"(a0), "r"(a1), "r"(a2), "r"(a3), "r"(b0), "r"(b1));
}
__device__ __forceinline__ void ldm_x4(uint32_t& r0, uint32_t& r1,
                                       uint32_t& r2, uint32_t& r3, uint32_t addr) {
    asm volatile("ldmatrix.sync.aligned.m8n8.x4.shared.b16 {%0,%1,%2,%3}, [%4];"
                 : "=r"(r0), "=r"(r1), "=r"(r2), "=r"(r3) : "r"(addr));
}
__device__ __forceinline__ uint32_t sh_addr(const void* p) {
    return (uint32_t)__cvta_generic_to_shared(p);
}
__device__ __forceinline__ uint32_t packh2(float a, float b) {
    __half2 h = __floats2half2_rn(a, b);
    return *(uint32_t*)&h;
}

// ---------------- prep: W1[129:193]^T -> fp16 [n][k] ------------------------
__global__ void prep_W1e(const float* __restrict__ W1, __half* __restrict__ W1e)
{
    int idx = blockIdx.x * 256 + threadIdx.x;    // LL*EFD = 16384
    if (idx >= LL * EFD) return;
    int n = idx >> 6, k = idx & 63;
    W1e[idx] = __float2half_rn(W1[(size_t)(KXW + k) * LL + n]);
}

// ---------------- edge GEMM (K=64, fp16 mma + ldmatrix, pipelined) ----------
// smem: As half[128][72]=18432, Bs half[64][72]=9216, XWs half[128][72]=18432,
//       rIdx 512, stats 2048 -> 48640 bytes
#define ESA    0
#define ESB    18432
#define ESXW   27648
#define ESRIDX 46080
#define ESSTAT 46592
#define E_SMEM 48640

__global__ void __launch_bounds__(256) edge_gemm(
    const float* __restrict__ eattr, const int* __restrict__ erow,
    const __half* __restrict__ W1e, const __half* __restrict__ XW,
    __half* __restrict__ Y1,
    float* __restrict__ gsum, float* __restrict__ gsq)
{
    extern __shared__ char smem[];
    __half (*As)[72]    = (__half(*)[72])(smem + ESA);
    __half (*Bs)[72]    = (__half(*)[72])(smem + ESB);
    __half (*XWs)[72]   = (__half(*)[72])(smem + ESXW);
    int*   rIdx = (int*)  (smem + ESRIDX);
    float* sSum = (float*)(smem + ESSTAT);
    float* sSq  = (float*)(smem + ESSTAT + 1024);

    const int tid  = threadIdx.x;
    const int wid  = tid >> 5, lane = tid & 31;
    const int gid  = lane >> 2, tg = lane & 3;
    const int m0   = blockIdx.x * 128;
    const int wm   = (wid & 3) * 32;
    const int wn   = (wid >> 2) * 32;

    if (tid < 128) rIdx[tid] = erow[m0 + tid];
    sSum[tid] = 0.f; sSq[tid] = 0.f;

    // ldmatrix lane-address bases (row/k-half decomposition)
    const int aRow = lane & 15, aKo = (lane >> 4) * 8;
    const int bRow = (lane & 7) + (lane >> 4) * 8, bKo = ((lane >> 3) & 1) * 8;
    const uint32_t aAddr0 = sh_addr(&As[wm + aRow][aKo]);
    const uint32_t aAddr1 = sh_addr(&As[wm + 16 + aRow][aKo]);
    const uint32_t bAddr0 = sh_addr(&Bs[wn + bRow][bKo]);
    const uint32_t bAddr1 = sh_addr(&Bs[wn + 16 + bRow][bKo]);

    // stage eattr tile [128 x 64] as fp16 (coalesced float4)
    #pragma unroll
    for (int it = 0; it < 8; it++) {
        int idx = tid + it * 256;
        int row = idx >> 4, q = idx & 15;
        float4 v = *(const float4*)(eattr + (size_t)(m0 + row) * EFD + 4 * q);
        uint2 t; t.x = packh2(v.x, v.y); t.y = packh2(v.z, v.w);
        *(uint2*)&As[row][4 * q] = t;
    }
    __syncthreads();

    // stage ct=0 B and XW tiles
    #pragma unroll
    for (int it = 0; it < 2; it++) {
        int idx = tid + it * 256;
        int n = idx >> 3, q = idx & 7;
        *(uint4*)&Bs[n][8 * q] = *(const uint4*)(W1e + (size_t)n * EFD + 8 * q);
    }
    #pragma unroll
    for (int it = 0; it < 8; it++) {
        int idx = tid + it * 256;
        int row = idx >> 4, q = idx & 15;
        *(uint2*)&XWs[row][4 * q] = *(const uint2*)(XW + (size_t)rIdx[row] * LL + 4 * q);
    }
    __syncthreads();

    for (int ct = 0; ct < 4; ct++) {
        const int n0 = ct * 64;

        // prefetch next tile's B + XW into registers (overlaps with MMA below)
        uint4 pb[2];
        uint2 px[8];
        if (ct < 3) {
            const int n1 = n0 + 64;
            #pragma unroll
            for (int it = 0; it < 2; it++) {
                int idx = tid + it * 256;
                int n = idx >> 3, q = idx & 7;
                pb[it] = *(const uint4*)(W1e + (size_t)(n1 + n) * EFD + 8 * q);
            }
            #pragma unroll
            for (int it = 0; it < 8; it++) {
                int idx = tid + it * 256;
                int row = idx >> 4, q = idx & 15;
                px[it] = *(const uint2*)(XW + (size_t)rIdx[row] * LL + n1 + 4 * q);
            }
        }

        float c[2][4][4];
        #pragma unroll
        for (int i = 0; i < 2; i++)
            #pragma unroll
            for (int j = 0; j < 4; j++)
                #pragma unroll
                for (int k = 0; k < 4; k++) c[i][j][k] = 0.f;

        #pragma unroll
        for (int ks = 0; ks < 64; ks += 16) {
            uint32_t a[2][4], b[4][2];
            ldm_x4(a[0][0], a[0][1], a[0][2], a[0][3], aAddr0 + ks * 2);
            ldm_x4(a[1][0], a[1][1], a[1][2], a[1][3], aAddr1 + ks * 2);
            ldm_x4(b[0][0], b[0][1], b[1][0], b[1][1], bAddr0 + ks * 2);
            ldm_x4(b[2][0], b[2][1], b[3][0], b[3][1], bAddr1 + ks * 2);
            #pragma unroll
            for (int mt = 0; mt < 2; mt++)
                #pragma unroll
                for (int nt = 0; nt < 4; nt++)
                    mma_h(c[mt][nt], a[mt][0], a[mt][1], a[mt][2], a[mt][3],
                          b[nt][0], b[nt][1]);
        }

        // epilogue: add gathered XW rows (fp16->fp32), write Y1, BN stats
        float ls[8], lq[8];
        #pragma unroll
        for (int s = 0; s < 8; s++) { ls[s] = 0.f; lq[s] = 0.f; }
        #pragma unroll
        for (int mt = 0; mt < 2; mt++) {
            int r0 = wm + mt * 16 + gid;
            int r1 = r0 + 8;
            #pragma unroll
            for (int nt = 0; nt < 4; nt++) {
                int cb = wn + nt * 8 + 2 * tg;
                float2 x0 = __half22float2(*(__half2*)&XWs[r0][cb]);
                float2 x1 = __half22float2(*(__half2*)&XWs[r1][cb]);
                float v00 = c[mt][nt][0] + x0.x;
                float v01 = c[mt][nt][1] + x0.y;
                float v10 = c[mt][nt][2] + x1.x;
                float v11 = c[mt][nt][3] + x1.y;
                *(__half2*)(Y1 + (size_t)(m0 + r0) * LL + n0 + cb) = __floats2half2_rn(v00, v01);
                *(__half2*)(Y1 + (size_t)(m0 + r1) * LL + n0 + cb) = __floats2half2_rn(v10, v11);
                ls[nt * 2 + 0] += v00 + v10;  lq[nt * 2 + 0] += v00 * v00 + v10 * v10;
                ls[nt * 2 + 1] += v01 + v11;  lq[nt * 2 + 1] += v01 * v01 + v11 * v11;
            }
        }
        #pragma unroll
        for (int mask = 4; mask <= 16; mask <<= 1)
            #pragma unroll
            for (int s = 0; s < 8; s++) {
                ls[s] += __shfl_xor_sync(0xffffffffu, ls[s], mask);
                lq[s] += __shfl_xor_sync(0xffffffffu, lq[s], mask);
            }
        if (gid == 0) {
            #pragma unroll
            for (int nt = 0; nt < 4; nt++)
                #pragma unroll
                for (int h = 0; h < 2; h++) {
                    int col = n0 + wn + nt * 8 + 2 * tg + h;
                    atomicAdd(&sSum[col], ls[nt * 2 + h]);
                    atomicAdd(&sSq[col],  lq[nt * 2 + h]);
                }
        }
        __syncthreads();

        // commit prefetched tiles to smem for next iteration
        if (ct < 3) {
            #pragma unroll
            for (int it = 0; it < 2; it++) {
                int idx = tid + it * 256;
                int n = idx >> 3, q = idx & 7;
                *(uint4*)&Bs[n][8 * q] = pb[it];
            }
            #pragma unroll
            for (int it = 0; it < 8; it++) {
                int idx = tid + it * 256;
                int row = idx >> 4, q = idx & 15;
                *(uint2*)&XWs[row][4 * q] = px[it];
            }
            __syncthreads();
        }
    }
    atomicAdd(&gsum[tid], sSum[tid]);
    atomicAdd(&gsq[tid],  sSq[tid]);
}

// ---------------- generic fp16-mma GEMM, k16, double-buffered, ldmatrix -----
//   MODE 1: node rows  = [x[m], batch[m], agg[m]]  + fused BN2 stats, Y2 fp16 out
//   MODE 2: relu(bn(Y2[m])) from fp16 Y2  (fp32 output)
//   MODE 3: xw rows    = [x[m], batch[m]]          (XW, fp16 output)
template<int MODE>
__global__ void __launch_bounds__(256) gemm_f16(int M, int Nc, int K,
    const float* __restrict__ B, const float* __restrict__ bias,
    float* __restrict__ C, __half* __restrict__ Ch,
    const float* __restrict__ x, const int* __restrict__ batch,
    const float* __restrict__ agg,
    const __half* __restrict__ Y2,
    const float* __restrict__ scale, const float* __restrict__ shift,
    float* __restrict__ gsum, float* __restrict__ gsq,
    int relu_out)
{
    __shared__ __half As[2][128][24];
    __shared__ __half Bs[2][64][24];

    const int tid = threadIdx.x;
    const int wid = tid >> 5, lane = tid & 31;
    const int gid = lane >> 2, tg = lane & 3;
    const int m0  = blockIdx.x * 128, n0 = blockIdx.y * 64;
    const int wm  = (wid & 3) * 32;
    const int wn  = (wid >> 2) * 32;

    float c[2][4][4];
    #pragma unroll
    for (int i = 0; i < 2; i++)
        #pragma unroll
        for (int j = 0; j < 4; j++)
            #pragma unroll
            for (int k = 0; k < 4; k++) c[i][j][k] = 0.f;

    const int kk = tid & 15;
    const int mb = tid >> 4;
    const int bn = tid & 63;
    const int bk = tid >> 6;

    // ldmatrix lane-address bases per buffer
    const int aRow = lane & 15, aKo = (lane >> 4) * 8;
    const int bRow = (lane & 7) + (lane >> 4) * 8, bKo = ((lane >> 3) & 1) * 8;
    uint32_t aAddr[2], bAddr[2];
    #pragma unroll
    for (int pp = 0; pp < 2; pp++) {
        aAddr[pp] = sh_addr(&As[pp][wm + aRow][aKo]);
        bAddr[pp] = sh_addr(&Bs[pp][wn + bRow][bKo]);
    }
    const uint32_t aStep = 16 * 24 * 2;   // 16 rows stride in bytes
    const uint32_t bStep = 16 * 24 * 2;

    auto loadA = [&](int k0, float* av) {
        int gk = k0 + kk;
        #pragma unroll
        for (int i = 0; i < 8; i++) {
            int mm = mb + i * 16;
            int gm = m0 + mm;
            float v = 0.f;
            if (gm < M && gk < K) {
                if (MODE == 1) {
                    if (gk < NFD)       v = x[(size_t)gm * NFD + gk];
                    else if (gk == NFD) v = (float)batch[gm];
                    else                v = agg[(size_t)gm * LL + (gk - NFD - 1)];
                } else if (MODE == 3) {
                    if (gk < NFD)       v = x[(size_t)gm * NFD + gk];
                    else                v = (float)batch[gm];
                } else {
                    float y = __half2float(Y2[(size_t)gm * DD2 + gk]);
                    v = fmaxf(fmaf(y, scale[gk], shift[gk]), 0.f);
                }
            }
            av[i] = v;
        }
    };
    auto loadB = [&](int k0, float* bv) {
        #pragma unroll
        for (int i = 0; i < 4; i++) {
            int k = bk + i * 4;
            int gkb = k0 + k;
            int gn = n0 + bn;
            bv[i] = (gkb < K && gn < Nc) ? B[(size_t)gkb * Nc + gn] : 0.f;
        }
    };

    float av[8], bv[4];
    loadA(0, av);
    loadB(0, bv);
    #pragma unroll
    for (int i = 0; i < 8; i++) As[0][mb + i * 16][kk] = __float2half_rn(av[i]);
    #pragma unroll
    for (int i = 0; i < 4; i++) Bs[0][bn][bk + i * 4] = __float2half_rn(bv[i]);
    __syncthreads();

    int p = 0;
    for (int k0 = 0; k0 < K; k0 += 16) {
        const bool more = (k0 + 16 < K);
        if (more) { loadA(k0 + 16, av); loadB(k0 + 16, bv); }

        {
            uint32_t a[2][4], b[4][2];
            ldm_x4(a[0][0], a[0][1], a[0][2], a[0][3], aAddr[p]);
            ldm_x4(a[1][0], a[1][1], a[1][2], a[1][3], aAddr[p] + aStep);
            ldm_x4(b[0][0], b[0][1], b[1][0], b[1][1], bAddr[p]);
            ldm_x4(b[2][0], b[2][1], b[3][0], b[3][1], bAddr[p] + bStep);
            #pragma unroll
            for (int mt = 0; mt < 2; mt++)
                #pragma unroll
                for (int nt = 0; nt < 4; nt++)
                    mma_h(c[mt][nt], a[mt][0], a[mt][1], a[mt][2], a[mt][3],
                          b[nt][0], b[nt][1]);
        }

        if (more) {
            int q = p ^ 1;
            #pragma unroll
            for (int i = 0; i < 8; i++) As[q][mb + i * 16][kk] = __float2half_rn(av[i]);
            #pragma unroll
            for (int i = 0; i < 4; i++) Bs[q][bn][bk + i * 4] = __float2half_rn(bv[i]);
            __syncthreads();
            p = q;
        }
    }

    float ls[8], lq[8];
    if (MODE == 1) {
        #pragma unroll
        for (int s = 0; s < 8; s++) { ls[s] = 0.f; lq[s] = 0.f; }
    }
    #pragma unroll
    for (int mt = 0; mt < 2; mt++) {
        int r0 = m0 + wm + mt * 16 + gid;
        int r1 = r0 + 8;
        #pragma unroll
        for (int nt = 0; nt < 4; nt++) {
            int cb = wn + nt * 8 + 2 * tg;
            if (MODE == 3) {
                float b0 = bias[n0 + cb], b1 = bias[n0 + cb + 1];
                if (r0 < M)
                    *(__half2*)(Ch + (size_t)r0 * Nc + n0 + cb) =
                        __floats2half2_rn(c[mt][nt][0] + b0, c[mt][nt][1] + b1);
                if (r1 < M)
                    *(__half2*)(Ch + (size_t)r1 * Nc + n0 + cb) =
                        __floats2half2_rn(c[mt][nt][2] + b0, c[mt][nt][3] + b1);
            } else {
                #pragma unroll
                for (int h = 0; h < 2; h++) {
                    int col = n0 + cb + h;
                    if (col >= Nc) continue;
                    float bb = bias[col];
                    if (r0 < M) {
                        float v = c[mt][nt][h] + bb;
                        if (relu_out) v = fmaxf(v, 0.f);
                        if (MODE == 1) {
                            Ch[(size_t)r0 * Nc + col] = __float2half_rn(v);
                            ls[nt * 2 + h] += v; lq[nt * 2 + h] += v * v;
                        } else {
                            C[(size_t)r0 * Nc + col] = v;
                        }
                    }
                    if (r1 < M) {
                        float v = c[mt][nt][2 + h] + bb;
                        if (relu_out) v = fmaxf(v, 0.f);
                        if (MODE == 1) {
                            Ch[(size_t)r1 * Nc + col] = __float2half_rn(v);
                            ls[nt * 2 + h] += v; lq[nt * 2 + h] += v * v;
                        } else {
                            C[(size_t)r1 * Nc + col] = v;
                        }
                    }
                }
            }
        }
    }
    if (MODE == 1) {
        #pragma unroll
        for (int mask = 4; mask <= 16; mask <<= 1)
            #pragma unroll
            for (int s = 0; s < 8; s++) {
                ls[s] += __shfl_xor_sync(0xffffffffu, ls[s], mask);
                lq[s] += __shfl_xor_sync(0xffffffffu, lq[s], mask);
            }
        if (gid == 0) {
            #pragma unroll
            for (int nt = 0; nt < 4; nt++)
                #pragma unroll
                for (int h = 0; h < 2; h++) {
                    int col = n0 + wn + nt * 8 + 2 * tg + h;
                    if (col < Nc) {
                        atomicAdd(&gsum[col], ls[nt * 2 + h]);
                        atomicAdd(&gsq[col],  lq[nt * 2 + h]);
                    }
                }
        }
    }
}

// ---------------- BN finalize / CSR / gather --------------------------------
__global__ void finalize_kernel(const float* __restrict__ sum, const float* __restrict__ sumsq,
                                int M, int C,
                                const float* __restrict__ gamma, const float* __restrict__ beta,
                                float* __restrict__ scale, float* __restrict__ shift)
{
    int c = blockIdx.x * blockDim.x + threadIdx.x;
    if (c < C) {
        float mu  = sum[c] / (float)M;
        float var = sumsq[c] / (float)M - mu * mu;
        float sc  = rsqrtf(var + BNEPS) * gamma[c];
        scale[c] = sc;
        shift[c] = beta[c] - mu * sc;
    }
}

__global__ void cnt_kernel(const int* __restrict__ col, int* __restrict__ cnt)
{
    int e = blockIdx.x * blockDim.x + threadIdx.x;
    if (e < NE) atomicAdd(&cnt[col[e]], 1);
}

__global__ void scan_kernel(const int* __restrict__ cnt,
                            int* __restrict__ off, int* __restrict__ cur)
{
    __shared__ int warpsum[32];
    __shared__ int base_s;
    int tid = threadIdx.x, lane = tid & 31, w = tid >> 5;
    if (tid == 0) base_s = 0;
    __syncthreads();
    for (int c0 = 0; c0 < NN; c0 += 1024) {
        int i = c0 + tid;
        int v = (i < NN) ? cnt[i] : 0;
        int inc = v;
        #pragma unroll
        for (int s = 1; s < 32; s <<= 1) {
            int t = __shfl_up_sync(0xffffffffu, inc, s);
            if (lane >= s) inc += t;
        }
        if (lane == 31) warpsum[w] = inc;
        __syncthreads();
        if (w == 0) {
            int ws = warpsum[lane];
            #pragma unroll
            for (int s = 1; s < 32; s <<= 1) {
                int t = __shfl_up_sync(0xffffffffu, ws, s);
                if (lane >= s) ws += t;
            }
            warpsum[lane] = ws;
        }
        __syncthreads();
        int base = base_s;
        int wexc = (w > 0) ? warpsum[w - 1] : 0;
        int excl = base + wexc + inc - v;
        if (i < NN) { off[i] = excl; cur[i] = excl; }
        int total = warpsum[31];
        __syncthreads();
        if (tid == 0) base_s = base + total;
        __syncthreads();
    }
    if (threadIdx.x == 0) off[NN] = base_s;
}

__global__ void bucket_kernel(const int* __restrict__ col,
                              int* __restrict__ cur, int* __restrict__ eid)
{
    int e = blockIdx.x * blockDim.x + threadIdx.x;
    if (e < NE) {
        int pos = atomicAdd(&cur[col[e]], 1);
        eid[pos] = e;
    }
}

// per-node gather-sum of relu(bn(Y1)) rows (fp16 Y1), 2-way unrolled, mean
__global__ void __launch_bounds__(256) gather_kernel(
    const __half* __restrict__ Y1,
    const int* __restrict__ eid, const int* __restrict__ off,
    const float* __restrict__ scale, const float* __restrict__ shift,
    float* __restrict__ ssum)
{
    __shared__ float4 part[4][64];
    const int n   = blockIdx.x;
    const int sub = threadIdx.x >> 6;
    const int cgi = threadIdx.x & 63;
    const int cg  = cgi << 2;
    const int s = off[n], e = off[n + 1];

    float4 sc = *(const float4*)(scale + cg);
    float4 sh = *(const float4*)(shift + cg);
    float4 acc = make_float4(0.f, 0.f, 0.f, 0.f);
    float4 acc2 = make_float4(0.f, 0.f, 0.f, 0.f);

    int j = s + sub;
    for (; j + 4 < e; j += 8) {
        int e0 = eid[j], e1 = eid[j + 4];
        uint2 r0 = *(const uint2*)(Y1 + (size_t)e0 * LL + cg);
        uint2 r1 = *(const uint2*)(Y1 + (size_t)e1 * LL + cg);
        __half2* p0 = (__half2*)&r0;
        __half2* p1 = (__half2*)&r1;
        float2 a0 = __half22float2(p0[0]), a1 = __half22float2(p0[1]);
        float2 b0 = __half22float2(p1[0]), b1 = __half22float2(p1[1]);
        acc.x  += fmaxf(fmaf(a0.x, sc.x, sh.x), 0.f);
        acc.y  += fmaxf(fmaf(a0.y, sc.y, sh.y), 0.f);
        acc.z  += fmaxf(fmaf(a1.x, sc.z, sh.z), 0.f);
        acc.w  += fmaxf(fmaf(a1.y, sc.w, sh.w), 0.f);
        acc2.x += fmaxf(fmaf(b0.x, sc.x, sh.x), 0.f);
        acc2.y += fmaxf(fmaf(b0.y, sc.y, sh.y), 0.f);
        acc2.z += fmaxf(fmaf(b1.x, sc.z, sh.z), 0.f);
        acc2.w += fmaxf(fmaf(b1.y, sc.w, sh.w), 0.f);
    }
    if (j < e) {
        int e0 = eid[j];
        uint2 r0 = *(const uint2*)(Y1 + (size_t)e0 * LL + cg);
        __half2* p0 = (__half2*)&r0;
        float2 a0 = __half22float2(p0[0]), a1 = __half22float2(p0[1]);
        acc.x += fmaxf(fmaf(a0.x, sc.x, sh.x), 0.f);
        acc.y += fmaxf(fmaf(a0.y, sc.y, sh.y), 0.f);
        acc.z += fmaxf(fmaf(a1.x, sc.z, sh.z), 0.f);
        acc.w += fmaxf(fmaf(a1.y, sc.w, sh.w), 0.f);
    }
    acc.x += acc2.x; acc.y += acc2.y; acc.z += acc2.z; acc.w += acc2.w;
    part[sub][cgi] = acc;
    __syncthreads();
    if (threadIdx.x < 64) {
        float4 a0 = part[0][threadIdx.x], a1 = part[1][threadIdx.x];
        float4 a2 = part[2][threadIdx.x], a3 = part[3][threadIdx.x];
        float inv = 1.f / (float)max(e - s, 1);
        float4 o;
        o.x = (a0.x + a1.x + a2.x + a3.x) * inv;
        o.y = (a0.y + a1.y + a2.y + a3.y) * inv;
        o.z = (a0.z + a1.z + a2.z + a3.z) * inv;
        o.w = (a0.w + a1.w + a2.w + a3.w) * inv;
        *(float4*)(ssum + (size_t)n * LL + (threadIdx.x << 2)) = o;
    }
}

extern "C" void kernel_launch(void* const* d_in, const int* in_sizes, int n_in,
                              void* d_out, int out_size)
{
    const float* x     = (const float*)d_in[0];
    const int*   eidx  = (const int*)  d_in[1];
    const float* eattr = (const float*)d_in[2];
    const int*   batch = (const int*)  d_in[4];
    const float* W1  = (const float*)d_in[5];
    const float* b1  = (const float*)d_in[6];
    const float* g1  = (const float*)d_in[7];
    const float* be1 = (const float*)d_in[8];
    const float* W2  = (const float*)d_in[9];
    const float* b2  = (const float*)d_in[10];
    const float* g2  = (const float*)d_in[11];
    const float* be2 = (const float*)d_in[12];
    const float* W3  = (const float*)d_in[13];
    const float* b3  = (const float*)d_in[14];
    float* out = (float*)d_out;

    const int* erow = eidx;
    const int* ecol = eidx + NE;

    void *pY1, *pY2, *pXW, *pss, *pcnt, *poff, *pcur, *peid, *pW1e;
    void *ps1, *pq1, *psc1, *psh1, *ps2, *pq2, *psc2, *psh2;
    cudaGetSymbolAddress(&pY1,  g_Y1);
    cudaGetSymbolAddress(&pY2,  g_Y2);
    cudaGetSymbolAddress(&pXW,  g_XW);
    cudaGetSymbolAddress(&pss,  g_ssum);
    cudaGetSymbolAddress(&pcnt, g_cnt);
    cudaGetSymbolAddress(&poff, g_off);
    cudaGetSymbolAddress(&pcur, g_cur);
    cudaGetSymbolAddress(&peid, g_eid);
    cudaGetSymbolAddress(&pW1e, g_W1e);
    cudaGetSymbolAddress(&ps1,  g_sum1);   cudaGetSymbolAddress(&pq1,  g_sumsq1);
    cudaGetSymbolAddress(&psc1, g_scale1); cudaGetSymbolAddress(&psh1, g_shift1);
    cudaGetSymbolAddress(&ps2,  g_sum2);   cudaGetSymbolAddress(&pq2,  g_sumsq2);
    cudaGetSymbolAddress(&psc2, g_scale2); cudaGetSymbolAddress(&psh2, g_shift2);

    static cudaStream_t s2 = nullptr;
    static cudaEvent_t ev1 = nullptr, ev2 = nullptr;
    if (!s2) {
        cudaStreamCreateWithFlags(&s2, cudaStreamNonBlocking);
        cudaEventCreateWithFlags(&ev1, cudaEventDisableTiming);
        cudaEventCreateWithFlags(&ev2, cudaEventDisableTiming);
    }

    cudaMemsetAsync(ps1,  0, LL  * sizeof(float), 0);
    cudaMemsetAsync(pq1,  0, LL  * sizeof(float), 0);
    cudaMemsetAsync(ps2,  0, DD2 * sizeof(float), 0);
    cudaMemsetAsync(pq2,  0, DD2 * sizeof(float), 0);
    cudaMemsetAsync(pcnt, 0, NN  * sizeof(int),   0);

    cudaFuncSetAttribute(edge_gemm, cudaFuncAttributeMaxDynamicSharedMemorySize, E_SMEM);

    // ---- fork: CSR build on side stream
    cudaEventRecord(ev1, 0);
    cudaStreamWaitEvent(s2, ev1, 0);
    cnt_kernel<<<NE / 256, 256, 0, s2>>>(ecol, (int*)pcnt);
    scan_kernel<<<1, 1024, 0, s2>>>((int*)pcnt, (int*)poff, (int*)pcur);
    bucket_kernel<<<NE / 256, 256, 0, s2>>>(ecol, (int*)pcur, (int*)peid);
    cudaEventRecord(ev2, s2);

    // ---- main chain
    prep_W1e<<<(LL * EFD + 255) / 256, 256>>>(W1, (__half*)pW1e);

    gemm_f16<3><<<dim3((NN + 127) / 128, LL / 64), 256>>>(
        NN, LL, KXW, W1, b1, nullptr, (__half*)pXW,
        x, batch, nullptr, nullptr, nullptr, nullptr, nullptr, nullptr, 0);

    edge_gemm<<<NE / 128, 256, E_SMEM>>>(eattr, erow, (const __half*)pW1e,
                                         (const __half*)pXW, (__half*)pY1,
                                         (float*)ps1, (float*)pq1);
    finalize_kernel<<<2, 256>>>((float*)ps1, (float*)pq1, NE, LL, g1, be1,
                                (float*)psc1, (float*)psh1);

    // ---- join: gather needs CSR + Y1 + scale/shift
    cudaStreamWaitEvent(0, ev2, 0);
    gather_kernel<<<NN, 256>>>((const __half*)pY1, (int*)peid, (int*)poff,
                               (float*)psc1, (float*)psh1, (float*)pss);

    gemm_f16<1><<<dim3((NN + 127) / 128, (DD2 + 63) / 64), 256>>>(
        NN, DD2, DD2, W2, b2, nullptr, (__half*)pY2,
        x, batch, (float*)pss, nullptr, nullptr, nullptr,
        (float*)ps2, (float*)pq2, 0);

    finalize_kernel<<<2, 256>>>((float*)ps2, (float*)pq2, NN, DD2, g2, be2,
                                (float*)psc2, (float*)psh2);

    gemm_f16<2><<<dim3((NN + 127) / 128, NFD / 64), 256>>>(
        NN, NFD, DD2, W3, b3, out, nullptr,
        nullptr, batch, nullptr, (const __half*)pY2, (float*)psc2, (float*)psh2,
        nullptr, nullptr, 1);
}

// round 17
// speedup vs baseline: 1.0432x; 1.0432x over previous
#include <cuda_runtime.h>
#include <cuda_fp16.h>
#include <cstdint>
#include <math.h>

#define NN   50000      // nodes
#define NE   800000     // edges
#define NFD  128        // node feature size
#define EFD  64         // edge feature size
#define LL   256        // layer size (mlp1 out)
#define DD1  193        // mlp1 input dim
#define DD2  385        // mlp2 dim
#define KXW  129        // x + batch part of mlp1/mlp2 K
#define LDXW2 392       // padded row stride for XW2 (halves, 16B-aligned)
#define BNEPS 1e-5f

// ---------------- scratch (static device globals) ---------------------------
__device__ __half   g_Y1[(size_t)NE * LL];      // edge MLP pre-BN output (fp16)
__device__ __half   g_Y2[(size_t)NN * DD2];     // node MLP pre-BN output (fp16)
__device__ __half   g_XW[(size_t)NN * LL];      // node part of edge MLP (fp16)
__device__ __half   g_XW2[(size_t)NN * LDXW2];  // node-input part of node MLP (fp16)
__device__ float    g_ssum[(size_t)NN * LL];    // aggregated means
__device__ __half   g_W1e[LL * EFD];            // W1[129:193]^T as fp16, [n][k]
__device__ int      g_cnt[NN];
__device__ int      g_off[NN + 1];
__device__ int      g_cur[NN];
__device__ int      g_eid[NE];
__device__ float    g_sum1[LL],  g_sumsq1[LL],  g_scale1[LL],  g_shift1[LL];
__device__ float    g_sum2[DD2], g_sumsq2[DD2], g_scale2[DD2], g_shift2[DD2];

// ---------------- fp16 mma helpers ------------------------------------------
__device__ __forceinline__ void mma_h(float* c, uint32_t a0, uint32_t a1,
                                      uint32_t a2, uint32_t a3,
                                      uint32_t b0, uint32_t b1) {
    asm volatile(
        "mma.sync.aligned.m16n8k16.row.col.f32.f16.f16.f32 "
        "{%0,%1,%2,%3},{%4,%5,%6,%7},{%8,%9},{%0,%1,%2,%3};"
        : "+f"(c[0]), "+f"(c[1]), "+f"(c[2]), "+f"(c[3])
        : "r"(a0), "r"(a1), "r"(a2), "r"(a3), "r"(b0), "r"(b1));
}
__device__ __forceinline__ uint32_t ldh2(const __half* p) {
    return *(const uint32_t*)p;
}
__device__ __forceinline__ uint32_t packh2(float a, float b) {
    __half2 h = __floats2half2_rn(a, b);
    return *(uint32_t*)&h;
}

// ---------------- prep: W1[129:193]^T -> fp16 [n][k] ------------------------
__global__ void prep_W1e(const float* __restrict__ W1, __half* __restrict__ W1e)
{
    int idx = blockIdx.x * 256 + threadIdx.x;    // LL*EFD = 16384
    if (idx >= LL * EFD) return;
    int n = idx >> 6, k = idx & 63;
    W1e[idx] = __float2half_rn(W1[(size_t)(KXW + k) * LL + n]);
}

// ---------------- edge GEMM (K=64, fp16 mma, pipelined) ---------------------
// smem: As half[128][72]=18432, Bs half[64][72]=9216, XWs half[128][72]=18432,
//       rIdx 512, stats 2048 -> 48640 bytes
#define ESA    0
#define ESB    18432
#define ESXW   27648
#define ESRIDX 46080
#define ESSTAT 46592
#define E_SMEM 48640

__global__ void __launch_bounds__(256) edge_gemm(
    const float* __restrict__ eattr, const int* __restrict__ erow,
    const __half* __restrict__ W1e, const __half* __restrict__ XW,
    __half* __restrict__ Y1,
    float* __restrict__ gsum, float* __restrict__ gsq)
{
    extern __shared__ char smem[];
    __half (*As)[72]    = (__half(*)[72])(smem + ESA);
    __half (*Bs)[72]    = (__half(*)[72])(smem + ESB);
    __half (*XWs)[72]   = (__half(*)[72])(smem + ESXW);
    int*   rIdx = (int*)  (smem + ESRIDX);
    float* sSum = (float*)(smem + ESSTAT);
    float* sSq  = (float*)(smem + ESSTAT + 1024);

    const int tid  = threadIdx.x;
    const int wid  = tid >> 5, lane = tid & 31;
    const int gid  = lane >> 2, tg = lane & 3;
    const int m0   = blockIdx.x * 128;
    const int wm   = (wid & 3) * 32;
    const int wn   = (wid >> 2) * 32;

    if (tid < 128) rIdx[tid] = erow[m0 + tid];
    sSum[tid] = 0.f; sSq[tid] = 0.f;

    // stage eattr tile [128 x 64] as fp16 (coalesced float4)
    #pragma unroll
    for (int it = 0; it < 8; it++) {
        int idx = tid + it * 256;
        int row = idx >> 4, q = idx & 15;
        float4 v = *(const float4*)(eattr + (size_t)(m0 + row) * EFD + 4 * q);
        uint2 t; t.x = packh2(v.x, v.y); t.y = packh2(v.z, v.w);
        *(uint2*)&As[row][4 * q] = t;
    }
    __syncthreads();

    // stage ct=0 B and XW tiles
    #pragma unroll
    for (int it = 0; it < 2; it++) {
        int idx = tid + it * 256;
        int n = idx >> 3, q = idx & 7;
        *(uint4*)&Bs[n][8 * q] = *(const uint4*)(W1e + (size_t)n * EFD + 8 * q);
    }
    #pragma unroll
    for (int it = 0; it < 8; it++) {
        int idx = tid + it * 256;
        int row = idx >> 4, q = idx & 15;
        *(uint2*)&XWs[row][4 * q] = *(const uint2*)(XW + (size_t)rIdx[row] * LL + 4 * q);
    }
    __syncthreads();

    for (int ct = 0; ct < 4; ct++) {
        const int n0 = ct * 64;

        // prefetch next tile's B + XW into registers (overlaps with MMA below)
        uint4 pb[2];
        uint2 px[8];
        if (ct < 3) {
            const int n1 = n0 + 64;
            #pragma unroll
            for (int it = 0; it < 2; it++) {
                int idx = tid + it * 256;
                int n = idx >> 3, q = idx & 7;
                pb[it] = *(const uint4*)(W1e + (size_t)(n1 + n) * EFD + 8 * q);
            }
            #pragma unroll
            for (int it = 0; it < 8; it++) {
                int idx = tid + it * 256;
                int row = idx >> 4, q = idx & 15;
                px[it] = *(const uint2*)(XW + (size_t)rIdx[row] * LL + n1 + 4 * q);
            }
        }

        float c[2][4][4];
        #pragma unroll
        for (int i = 0; i < 2; i++)
            #pragma unroll
            for (int j = 0; j < 4; j++)
                #pragma unroll
                for (int k = 0; k < 4; k++) c[i][j][k] = 0.f;

        #pragma unroll
        for (int ks = 0; ks < 64; ks += 16) {
            uint32_t a[2][4], b[4][2];
            #pragma unroll
            for (int mt = 0; mt < 2; mt++) {
                int r = wm + mt * 16;
                a[mt][0] = ldh2(&As[r + gid][ks + 2 * tg]);
                a[mt][1] = ldh2(&As[r + gid + 8][ks + 2 * tg]);
                a[mt][2] = ldh2(&As[r + gid][ks + 8 + 2 * tg]);
                a[mt][3] = ldh2(&As[r + gid + 8][ks + 8 + 2 * tg]);
            }
            #pragma unroll
            for (int nt = 0; nt < 4; nt++) {
                int cc = wn + nt * 8;
                b[nt][0] = ldh2(&Bs[cc + gid][ks + 2 * tg]);
                b[nt][1] = ldh2(&Bs[cc + gid][ks + 8 + 2 * tg]);
            }
            #pragma unroll
            for (int mt = 0; mt < 2; mt++)
                #pragma unroll
                for (int nt = 0; nt < 4; nt++)
                    mma_h(c[mt][nt], a[mt][0], a[mt][1], a[mt][2], a[mt][3],
                          b[nt][0], b[nt][1]);
        }

        // epilogue: add gathered XW rows (fp16->fp32), write Y1, BN stats
        float ls[8], lq[8];
        #pragma unroll
        for (int s = 0; s < 8; s++) { ls[s] = 0.f; lq[s] = 0.f; }
        #pragma unroll
        for (int mt = 0; mt < 2; mt++) {
            int r0 = wm + mt * 16 + gid;
            int r1 = r0 + 8;
            #pragma unroll
            for (int nt = 0; nt < 4; nt++) {
                int cb = wn + nt * 8 + 2 * tg;
                float2 x0 = __half22float2(*(__half2*)&XWs[r0][cb]);
                float2 x1 = __half22float2(*(__half2*)&XWs[r1][cb]);
                float v00 = c[mt][nt][0] + x0.x;
                float v01 = c[mt][nt][1] + x0.y;
                float v10 = c[mt][nt][2] + x1.x;
                float v11 = c[mt][nt][3] + x1.y;
                *(__half2*)(Y1 + (size_t)(m0 + r0) * LL + n0 + cb) = __floats2half2_rn(v00, v01);
                *(__half2*)(Y1 + (size_t)(m0 + r1) * LL + n0 + cb) = __floats2half2_rn(v10, v11);
                ls[nt * 2 + 0] += v00 + v10;  lq[nt * 2 + 0] += v00 * v00 + v10 * v10;
                ls[nt * 2 + 1] += v01 + v11;  lq[nt * 2 + 1] += v01 * v01 + v11 * v11;
            }
        }
        #pragma unroll
        for (int mask = 4; mask <= 16; mask <<= 1)
            #pragma unroll
            for (int s = 0; s < 8; s++) {
                ls[s] += __shfl_xor_sync(0xffffffffu, ls[s], mask);
                lq[s] += __shfl_xor_sync(0xffffffffu, lq[s], mask);
            }
        if (gid == 0) {
            #pragma unroll
            for (int nt = 0; nt < 4; nt++)
                #pragma unroll
                for (int h = 0; h < 2; h++) {
                    int col = n0 + wn + nt * 8 + 2 * tg + h;
                    atomicAdd(&sSum[col], ls[nt * 2 + h]);
                    atomicAdd(&sSq[col],  lq[nt * 2 + h]);
                }
        }
        __syncthreads();

        // commit prefetched tiles to smem for next iteration
        if (ct < 3) {
            #pragma unroll
            for (int it = 0; it < 2; it++) {
                int idx = tid + it * 256;
                int n = idx >> 3, q = idx & 7;
                *(uint4*)&Bs[n][8 * q] = pb[it];
            }
            #pragma unroll
            for (int it = 0; it < 8; it++) {
                int idx = tid + it * 256;
                int row = idx >> 4, q = idx & 15;
                *(uint2*)&XWs[row][4 * q] = px[it];
            }
            __syncthreads();
        }
    }
    atomicAdd(&gsum[tid], sSum[tid]);
    atomicAdd(&gsq[tid],  sSq[tid]);
}

// ---------------- generic fp16-mma GEMM, k16, reg-prefetch pipeline ---------
//   MODE 2: A = relu(bn(Y2[m])) from fp16 Y2        -> fp32 C (final out)
//   MODE 3: A = [x[m], batch[m]]                    -> fp16 Ch, stride ldC (guarded)
//   MODE 4: A = agg[m] (K=256), epilogue += XW2 row -> fp16 Ch (Y2) + BN2 stats
template<int MODE>
__global__ void __launch_bounds__(256) gemm_f16(int M, int Nc, int K,
    const float* __restrict__ B, const float* __restrict__ bias,
    float* __restrict__ C, __half* __restrict__ Ch, int ldC,
    const float* __restrict__ x, const int* __restrict__ batch,
    const float* __restrict__ agg,
    const __half* __restrict__ Y2,
    const __half* __restrict__ XW2add,
    const float* __restrict__ scale, const float* __restrict__ shift,
    float* __restrict__ gsum, float* __restrict__ gsq,
    int relu_out)
{
    __shared__ __half As[128][24];
    __shared__ __half Bs[64][24];

    const int tid = threadIdx.x;
    const int wid = tid >> 5, lane = tid & 31;
    const int gid = lane >> 2, tg = lane & 3;
    const int m0  = blockIdx.x * 128, n0 = blockIdx.y * 64;
    const int wm  = (wid & 3) * 32;
    const int wn  = (wid >> 2) * 32;

    float c[2][4][4];
    #pragma unroll
    for (int i = 0; i < 2; i++)
        #pragma unroll
        for (int j = 0; j < 4; j++)
            #pragma unroll
            for (int k = 0; k < 4; k++) c[i][j][k] = 0.f;

    const int kk = tid & 15;
    const int mb = tid >> 4;
    const int bn = tid & 63;
    const int bk = tid >> 6;

    auto loadA = [&](int k0, float* av) {
        int gk = k0 + kk;
        #pragma unroll
        for (int i = 0; i < 8; i++) {
            int mm = mb + i * 16;
            int gm = m0 + mm;
            float v = 0.f;
            if (gm < M && gk < K) {
                if (MODE == 4) {
                    v = agg[(size_t)gm * LL + gk];
                } else if (MODE == 3) {
                    if (gk < NFD)       v = x[(size_t)gm * NFD + gk];
                    else                v = (float)batch[gm];
                } else {
                    float y = __half2float(Y2[(size_t)gm * DD2 + gk]);
                    v = fmaxf(fmaf(y, scale[gk], shift[gk]), 0.f);
                }
            }
            av[i] = v;
        }
    };
    auto loadB = [&](int k0, float* bv) {
        #pragma unroll
        for (int i = 0; i < 4; i++) {
            int k = bk + i * 4;
            int gkb = k0 + k;
            int gn = n0 + bn;
            bv[i] = (gkb < K && gn < Nc) ? B[(size_t)gkb * Nc + gn] : 0.f;
        }
    };

    float av[8], bv[4];
    loadA(0, av);
    loadB(0, bv);

    for (int k0 = 0; k0 < K; k0 += 16) {
        // commit current tile to smem
        #pragma unroll
        for (int i = 0; i < 8; i++) As[mb + i * 16][kk] = __float2half_rn(av[i]);
        #pragma unroll
        for (int i = 0; i < 4; i++) Bs[bn][bk + i * 4] = __float2half_rn(bv[i]);
        __syncthreads();

        // prefetch next tile (overlaps with MMA)
        if (k0 + 16 < K) { loadA(k0 + 16, av); loadB(k0 + 16, bv); }

        {
            uint32_t a[2][4], b[4][2];
            #pragma unroll
            for (int mt = 0; mt < 2; mt++) {
                int rr = wm + mt * 16;
                a[mt][0] = ldh2(&As[rr + gid][2 * tg]);
                a[mt][1] = ldh2(&As[rr + gid + 8][2 * tg]);
                a[mt][2] = ldh2(&As[rr + gid][8 + 2 * tg]);
                a[mt][3] = ldh2(&As[rr + gid + 8][8 + 2 * tg]);
            }
            #pragma unroll
            for (int nt = 0; nt < 4; nt++) {
                int cc = wn + nt * 8;
                b[nt][0] = ldh2(&Bs[cc + gid][2 * tg]);
                b[nt][1] = ldh2(&Bs[cc + gid][8 + 2 * tg]);
            }
            #pragma unroll
            for (int mt = 0; mt < 2; mt++)
                #pragma unroll
                for (int nt = 0; nt < 4; nt++)
                    mma_h(c[mt][nt], a[mt][0], a[mt][1], a[mt][2], a[mt][3],
                          b[nt][0], b[nt][1]);
        }
        __syncthreads();
    }

    float ls[8], lq[8];
    if (MODE == 4) {
        #pragma unroll
        for (int s = 0; s < 8; s++) { ls[s] = 0.f; lq[s] = 0.f; }
    }
    #pragma unroll
    for (int mt = 0; mt < 2; mt++) {
        int r0 = m0 + wm + mt * 16 + gid;
        int r1 = r0 + 8;
        #pragma unroll
        for (int nt = 0; nt < 4; nt++) {
            int cb = wn + nt * 8 + 2 * tg;
            if (MODE == 3) {
                // fp16 output with pad stride; guard against writing past row pad
                int colp = n0 + cb;
                if (colp + 2 <= ldC) {
                    float b0 = (colp     < Nc) ? bias[colp]     : 0.f;
                    float b1 = (colp + 1 < Nc) ? bias[colp + 1] : 0.f;
                    if (r0 < M)
                        *(__half2*)(Ch + (size_t)r0 * ldC + colp) =
                            __floats2half2_rn(c[mt][nt][0] + b0, c[mt][nt][1] + b1);
                    if (r1 < M)
                        *(__half2*)(Ch + (size_t)r1 * ldC + colp) =
                            __floats2half2_rn(c[mt][nt][2] + b0, c[mt][nt][3] + b1);
                }
            } else {
                #pragma unroll
                for (int h = 0; h < 2; h++) {
                    int col = n0 + cb + h;
                    if (col >= Nc) continue;
                    if (r0 < M) {
                        float v = c[mt][nt][h];
                        if (MODE == 4)
                            v += __half2float(XW2add[(size_t)r0 * LDXW2 + col]);
                        else
                            v += bias[col];
                        if (relu_out) v = fmaxf(v, 0.f);
                        if (MODE == 4) {
                            Ch[(size_t)r0 * Nc + col] = __float2half_rn(v);
                            ls[nt * 2 + h] += v; lq[nt * 2 + h] += v * v;
                        } else {
                            C[(size_t)r0 * Nc + col] = v;
                        }
                    }
                    if (r1 < M) {
                        float v = c[mt][nt][2 + h];
                        if (MODE == 4)
                            v += __half2float(XW2add[(size_t)r1 * LDXW2 + col]);
                        else
                            v += bias[col];
                        if (relu_out) v = fmaxf(v, 0.f);
                        if (MODE == 4) {
                            Ch[(size_t)r1 * Nc + col] = __float2half_rn(v);
                            ls[nt * 2 + h] += v; lq[nt * 2 + h] += v * v;
                        } else {
                            C[(size_t)r1 * Nc + col] = v;
                        }
                    }
                }
            }
        }
    }
    if (MODE == 4) {
        #pragma unroll
        for (int mask = 4; mask <= 16; mask <<= 1)
            #pragma unroll
            for (int s = 0; s < 8; s++) {
                ls[s] += __shfl_xor_sync(0xffffffffu, ls[s], mask);
                lq[s] += __shfl_xor_sync(0xffffffffu, lq[s], mask);
            }
        if (gid == 0) {
            #pragma unroll
            for (int nt = 0; nt < 4; nt++)
                #pragma unroll
                for (int h = 0; h < 2; h++) {
                    int col = n0 + wn + nt * 8 + 2 * tg + h;
                    if (col < Nc) {
                        atomicAdd(&gsum[col], ls[nt * 2 + h]);
                        atomicAdd(&gsq[col],  lq[nt * 2 + h]);
                    }
                }
        }
    }
}

// ---------------- BN finalize / CSR / gather --------------------------------
__global__ void finalize_kernel(const float* __restrict__ sum, const float* __restrict__ sumsq,
                                int M, int C,
                                const float* __restrict__ gamma, const float* __restrict__ beta,
                                float* __restrict__ scale, float* __restrict__ shift)
{
    int c = blockIdx.x * blockDim.x + threadIdx.x;
    if (c < C) {
        float mu  = sum[c] / (float)M;
        float var = sumsq[c] / (float)M - mu * mu;
        float sc  = rsqrtf(var + BNEPS) * gamma[c];
        scale[c] = sc;
        shift[c] = beta[c] - mu * sc;
    }
}

__global__ void cnt_kernel(const int* __restrict__ col, int* __restrict__ cnt)
{
    int e = blockIdx.x * blockDim.x + threadIdx.x;
    if (e < NE) atomicAdd(&cnt[col[e]], 1);
}

__global__ void scan_kernel(const int* __restrict__ cnt,
                            int* __restrict__ off, int* __restrict__ cur)
{
    __shared__ int warpsum[32];
    __shared__ int base_s;
    int tid = threadIdx.x, lane = tid & 31, w = tid >> 5;
    if (tid == 0) base_s = 0;
    __syncthreads();
    for (int c0 = 0; c0 < NN; c0 += 1024) {
        int i = c0 + tid;
        int v = (i < NN) ? cnt[i] : 0;
        int inc = v;
        #pragma unroll
        for (int s = 1; s < 32; s <<= 1) {
            int t = __shfl_up_sync(0xffffffffu, inc, s);
            if (lane >= s) inc += t;
        }
        if (lane == 31) warpsum[w] = inc;
        __syncthreads();
        if (w == 0) {
            int ws = warpsum[lane];
            #pragma unroll
            for (int s = 1; s < 32; s <<= 1) {
                int t = __shfl_up_sync(0xffffffffu, ws, s);
                if (lane >= s) ws += t;
            }
            warpsum[lane] = ws;
        }
        __syncthreads();
        int base = base_s;
        int wexc = (w > 0) ? warpsum[w - 1] : 0;
        int excl = base + wexc + inc - v;
        if (i < NN) { off[i] = excl; cur[i] = excl; }
        int total = warpsum[31];
        __syncthreads();
        if (tid == 0) base_s = base + total;
        __syncthreads();
    }
    if (threadIdx.x == 0) off[NN] = base_s;
}

__global__ void bucket_kernel(const int* __restrict__ col,
                              int* __restrict__ cur, int* __restrict__ eid)
{
    int e = blockIdx.x * blockDim.x + threadIdx.x;
    if (e < NE) {
        int pos = atomicAdd(&cur[col[e]], 1);
        eid[pos] = e;
    }
}

// per-node gather-sum of relu(bn(Y1)) rows (fp16 Y1), then mean
__global__ void __launch_bounds__(256) gather_kernel(
    const __half* __restrict__ Y1,
    const int* __restrict__ eid, const int* __restrict__ off,
    const float* __restrict__ scale, const float* __restrict__ shift,
    float* __restrict__ ssum)
{
    __shared__ float4 part[4][64];
    const int n   = blockIdx.x;
    const int sub = threadIdx.x >> 6;
    const int cgi = threadIdx.x & 63;
    const int cg  = cgi << 2;
    const int s = off[n], e = off[n + 1];

    float4 sc = *(const float4*)(scale + cg);
    float4 sh = *(const float4*)(shift + cg);
    float4 acc = make_float4(0.f, 0.f, 0.f, 0.f);

    for (int j = s + sub; j < e; j += 4) {
        int ej = eid[j];
        uint2 raw = *(const uint2*)(Y1 + (size_t)ej * LL + cg);
        __half2* ph = (__half2*)&raw;
        float2 y0 = __half22float2(ph[0]);
        float2 y1 = __half22float2(ph[1]);
        acc.x += fmaxf(fmaf(y0.x, sc.x, sh.x), 0.f);
        acc.y += fmaxf(fmaf(y0.y, sc.y, sh.y), 0.f);
        acc.z += fmaxf(fmaf(y1.x, sc.z, sh.z), 0.f);
        acc.w += fmaxf(fmaf(y1.y, sc.w, sh.w), 0.f);
    }
    part[sub][cgi] = acc;
    __syncthreads();
    if (threadIdx.x < 64) {
        float4 a0 = part[0][threadIdx.x], a1 = part[1][threadIdx.x];
        float4 a2 = part[2][threadIdx.x], a3 = part[3][threadIdx.x];
        float inv = 1.f / (float)max(e - s, 1);
        float4 o;
        o.x = (a0.x + a1.x + a2.x + a3.x) * inv;
        o.y = (a0.y + a1.y + a2.y + a3.y) * inv;
        o.z = (a0.z + a1.z + a2.z + a3.z) * inv;
        o.w = (a0.w + a1.w + a2.w + a3.w) * inv;
        *(float4*)(ssum + (size_t)n * LL + (threadIdx.x << 2)) = o;
    }
}

extern "C" void kernel_launch(void* const* d_in, const int* in_sizes, int n_in,
                              void* d_out, int out_size)
{
    const float* x     = (const float*)d_in[0];
    const int*   eidx  = (const int*)  d_in[1];
    const float* eattr = (const float*)d_in[2];
    const int*   batch = (const int*)  d_in[4];
    const float* W1  = (const float*)d_in[5];
    const float* b1  = (const float*)d_in[6];
    const float* g1  = (const float*)d_in[7];
    const float* be1 = (const float*)d_in[8];
    const float* W2  = (const float*)d_in[9];
    const float* b2  = (const float*)d_in[10];
    const float* g2  = (const float*)d_in[11];
    const float* be2 = (const float*)d_in[12];
    const float* W3  = (const float*)d_in[13];
    const float* b3  = (const float*)d_in[14];
    float* out = (float*)d_out;

    const int* erow = eidx;
    const int* ecol = eidx + NE;

    void *pY1, *pY2, *pXW, *pXW2, *pss, *pcnt, *poff, *pcur, *peid, *pW1e;
    void *ps1, *pq1, *psc1, *psh1, *ps2, *pq2, *psc2, *psh2;
    cudaGetSymbolAddress(&pY1,  g_Y1);
    cudaGetSymbolAddress(&pY2,  g_Y2);
    cudaGetSymbolAddress(&pXW,  g_XW);
    cudaGetSymbolAddress(&pXW2, g_XW2);
    cudaGetSymbolAddress(&pss,  g_ssum);
    cudaGetSymbolAddress(&pcnt, g_cnt);
    cudaGetSymbolAddress(&poff, g_off);
    cudaGetSymbolAddress(&pcur, g_cur);
    cudaGetSymbolAddress(&peid, g_eid);
    cudaGetSymbolAddress(&pW1e, g_W1e);
    cudaGetSymbolAddress(&ps1,  g_sum1);   cudaGetSymbolAddress(&pq1,  g_sumsq1);
    cudaGetSymbolAddress(&psc1, g_scale1); cudaGetSymbolAddress(&psh1, g_shift1);
    cudaGetSymbolAddress(&ps2,  g_sum2);   cudaGetSymbolAddress(&pq2,  g_sumsq2);
    cudaGetSymbolAddress(&psc2, g_scale2); cudaGetSymbolAddress(&psh2, g_shift2);

    static cudaStream_t s2 = nullptr;
    static cudaEvent_t ev1 = nullptr, ev2 = nullptr, ev3 = nullptr;
    if (!s2) {
        cudaStreamCreateWithFlags(&s2, cudaStreamNonBlocking);
        cudaEventCreateWithFlags(&ev1, cudaEventDisableTiming);
        cudaEventCreateWithFlags(&ev2, cudaEventDisableTiming);
        cudaEventCreateWithFlags(&ev3, cudaEventDisableTiming);
    }

    cudaMemsetAsync(ps1,  0, LL  * sizeof(float), 0);
    cudaMemsetAsync(pq1,  0, LL  * sizeof(float), 0);
    cudaMemsetAsync(ps2,  0, DD2 * sizeof(float), 0);
    cudaMemsetAsync(pq2,  0, DD2 * sizeof(float), 0);
    cudaMemsetAsync(pcnt, 0, NN  * sizeof(int),   0);

    cudaFuncSetAttribute(edge_gemm, cudaFuncAttributeMaxDynamicSharedMemorySize, E_SMEM);

    // ---- fork: CSR build + XW2 GEMM on side stream (input-only work)
    cudaEventRecord(ev1, 0);
    cudaStreamWaitEvent(s2, ev1, 0);
    cnt_kernel<<<NE / 256, 256, 0, s2>>>(ecol, (int*)pcnt);
    scan_kernel<<<1, 1024, 0, s2>>>((int*)pcnt, (int*)poff, (int*)pcur);
    bucket_kernel<<<NE / 256, 256, 0, s2>>>(ecol, (int*)pcur, (int*)peid);
    cudaEventRecord(ev2, s2);
    // XW2 = [x, batch] @ W2[0:129] + b2, fp16, padded stride LDXW2
    gemm_f16<3><<<dim3((NN + 127) / 128, (DD2 + 63) / 64), 256, 0, s2>>>(
        NN, DD2, KXW, W2, b2, nullptr, (__half*)pXW2, LDXW2,
        x, batch, nullptr, nullptr, nullptr, nullptr, nullptr,
        nullptr, nullptr, 0);
    cudaEventRecord(ev3, s2);

    // ---- main chain
    prep_W1e<<<(LL * EFD + 255) / 256, 256>>>(W1, (__half*)pW1e);

    gemm_f16<3><<<dim3((NN + 127) / 128, LL / 64), 256>>>(
        NN, LL, KXW, W1, b1, nullptr, (__half*)pXW, LL,
        x, batch, nullptr, nullptr, nullptr, nullptr, nullptr,
        nullptr, nullptr, 0);

    edge_gemm<<<NE / 128, 256, E_SMEM>>>(eattr, erow, (const __half*)pW1e,
                                         (const __half*)pXW, (__half*)pY1,
                                         (float*)ps1, (float*)pq1);
    finalize_kernel<<<2, 256>>>((float*)ps1, (float*)pq1, NE, LL, g1, be1,
                                (float*)psc1, (float*)psh1);

    // ---- join: gather needs CSR + Y1 + scale/shift
    cudaStreamWaitEvent(0, ev2, 0);
    gather_kernel<<<NN, 256>>>((const __half*)pY1, (int*)peid, (int*)poff,
                               (float*)psc1, (float*)psh1, (float*)pss);

    // ---- join: node GEMM needs XW2
    cudaStreamWaitEvent(0, ev3, 0);
    // Y2 = agg @ W2[129:385] + XW2  (K=256), fused BN2 stats
    gemm_f16<4><<<dim3((NN + 127) / 128, (DD2 + 63) / 64), 256>>>(
        NN, DD2, LL, W2 + (size_t)KXW * DD2, nullptr, nullptr, (__half*)pY2, DD2,
        nullptr, nullptr, (float*)pss, nullptr, (const __half*)pXW2,
        nullptr, nullptr, (float*)ps2, (float*)pq2, 0);

    finalize_kernel<<<2, 256>>>((float*)ps2, (float*)pq2, NN, DD2, g2, be2,
                                (float*)psc2, (float*)psh2);

    gemm_f16<2><<<dim3((NN + 127) / 128, NFD / 64), 256>>>(
        NN, NFD, DD2, W3, b3, out, nullptr, NFD,
        nullptr, nullptr, nullptr, (const __half*)pY2, nullptr,
        (float*)psc2, (float*)psh2, nullptr, nullptr, 1);
}